// round 12
// baseline (speedup 1.0000x reference)
#include <cuda_runtime.h>
#include <cuda_bf16.h>

// Problem constants
#define BATCH   8
#define HIN     256
#define WIN     256
#define DIM     64
#define IN_CH   192      // 3*DIM
#define HID_CH  384      // 2*IN_CH
#define HP      128      // H/2
#define WP      128      // W/2
#define NPIX    (BATCH*HP*WP)   // 131072
#define BN_EPS  1e-5f

// ---------------- scratch (no mallocs allowed) ----------------
__device__ float g_high   [NPIX * IN_CH];    // [p,192] high channels m: subband (64+m)%4 of orig ch (64+m)/4
__device__ float g_hidden [NPIX * HID_CH];   // [p,384]
__device__ float g_hidden2[NPIX * HID_CH];   // [p,384]
__device__ float g_sum    [2 * IN_CH];       // sum(192) | sumsq(192)
__device__ float g_wint   [IN_CH * HID_CH];  // w_in folded, [c,o] layout (192x384)
__device__ float g_b1     [HID_CH];
__device__ float g_woutt  [HID_CH * IN_CH];  // w_out transposed, [o,c] (384x192)

// ---------------- 0: zero stats (needed every graph replay) ----------------
__global__ void init_stats_kernel() {
    g_sum[threadIdx.x] = 0.0f;
}

// ---------------- 1: DWT (axis=2 stack semantics!) + passthrough + stats --
// Reference does jnp.stack([LL,LH,HL,HH], axis=2).reshape(B,4C,h,w):
//   merged channel u = c*4 + k  (c = orig channel, k = subband 0..3)
//   u in [0,64)    -> "LL" passthrough  = all 4 subbands of orig ch 0..15
//   u in [64,256)  -> "high" m = u-64   = all 4 subbands of orig ch 16..63
// grid 2048, block 64 (thread = orig channel). Each block: 64 pixels.
__global__ void dwt_kernel(const float* __restrict__ x, float* __restrict__ out) {
    const int c  = threadIdx.x;        // original channel 0..63
    const int p0 = blockIdx.x * 64;
    const bool hi = (c >= 16);
    float s0=0.f,s1=0.f,s2=0.f,s3=0.f, q0=0.f,q1=0.f,q2=0.f,q3=0.f;
    for (int pi = 0; pi < 64; ++pi) {
        const int p  = p0 + pi;
        const int b  = p >> 14;
        const int y  = (p >> 7) & 127;
        const int xw = p & 127;
        const int pixbase = (((b * HIN) + 2*y) * WIN + 2*xw) * DIM;
        const int ibase = pixbase + c;
        const float a  = x[ibase];
        const float bb = x[ibase + DIM];
        const float cc = x[ibase + WIN*DIM];
        const float dd = x[ibase + WIN*DIM + DIM];
        const float v0 = (a + bb + cc + dd) * 0.5f;  // LL
        const float v1 = (a - bb + cc - dd) * 0.5f;  // LH
        const float v2 = (a + bb - cc - dd) * 0.5f;  // HL
        const float v3 = (a - bb - cc + dd) * 0.5f;  // HH
        if (hi) {
            // high channels m = 4*(c-16) + k, contiguous float4
            *(float4*)(g_high + (size_t)p * IN_CH + 4*(c - 16)) =
                make_float4(v0, v1, v2, v3);
            s0 += v0; q0 += v0*v0;
            s1 += v1; q1 += v1*v1;
            s2 += v2; q2 += v2*v2;
            s3 += v3; q3 += v3*v3;
        } else {
            // passthrough: output phase (2y,2x), channels 4c..4c+3
            *(float4*)(out + pixbase + 4*c) = make_float4(v0, v1, v2, v3);
        }
    }
    if (hi) {
        const int m0 = 4 * (c - 16);
        atomicAdd(&g_sum[m0 + 0], s0);
        atomicAdd(&g_sum[m0 + 1], s1);
        atomicAdd(&g_sum[m0 + 2], s2);
        atomicAdd(&g_sum[m0 + 3], s3);
        atomicAdd(&g_sum[IN_CH + m0 + 0], q0);
        atomicAdd(&g_sum[IN_CH + m0 + 1], q1);
        atomicAdd(&g_sum[IN_CH + m0 + 2], q2);
        atomicAdd(&g_sum[IN_CH + m0 + 3], q3);
    }
}

// ---------------- 2: finalize BN stats, fold into w_in, transpose w_out ---
// grid 6, block 64. thread o = blockIdx.x*64+tid handles one hidden row.
__global__ void stats_fold_kernel(const float* __restrict__ cand0,
                                  const float* __restrict__ cand1,
                                  const float* __restrict__ w_in,
                                  const float* __restrict__ w_out) {
    __shared__ float s_scale[IN_CH];
    __shared__ float s_bias [IN_CH];
    const int tid = threadIdx.x;
    // gamma[0] = 1.0f (jnp.ones), beta[0] = 0.0f (jnp.zeros)
    const float* gamma = (cand0[0] != 0.0f) ? cand0 : cand1;
    const float* beta  = (cand0[0] != 0.0f) ? cand1 : cand0;
    const float invN = 1.0f / (float)NPIX;
    for (int c = tid; c < IN_CH; c += 64) {
        float mean = g_sum[c] * invN;
        float var  = g_sum[IN_CH + c] * invN - mean * mean;
        float sc   = gamma[c] * rsqrtf(var + BN_EPS);
        s_scale[c] = sc;
        s_bias[c]  = beta[c] - mean * sc;
    }
    __syncthreads();
    const int o = blockIdx.x * 64 + tid;  // 0..383
    float bacc = 0.f;
    for (int c = 0; c < IN_CH; ++c) {
        float w = w_in[o * IN_CH + c];
        g_wint[c * HID_CH + o] = w * s_scale[c];
        bacc += w * s_bias[c];
        g_woutt[o * IN_CH + c] = w_out[c * HID_CH + o];
    }
    g_b1[o] = bacc;
}

// ---------------- SGEMM tiling params ----------------
#define BM 128
#define BN 64
#define BK 8
// 256 threads: 16x16 grid, each thread 8 rows x 4 cols

// ---------------- 3: GEMM1  hidden = high @ w_in'^T + b1 ----------------
__global__ void __launch_bounds__(256)
gemm1_kernel() {
    __shared__ float As[BK][BM];
    __shared__ float Bs[BK][BN];
    const int K = IN_CH, N = HID_CH;
    const int tid  = threadIdx.x;
    const int row0 = blockIdx.x * BM;
    const int col0 = blockIdx.y * BN;
    const int tx = tid & 15, ty = tid >> 4;
    const int arow = tid >> 1, acol = (tid & 1) * 4;
    const int brow = tid >> 5, bcol = (tid & 31) * 2;
    float acc[8][4] = {};
    for (int k0 = 0; k0 < K; k0 += BK) {
        float4 av = *(const float4*)(g_high + (row0 + arow) * K + k0 + acol);
        As[acol + 0][arow] = av.x;
        As[acol + 1][arow] = av.y;
        As[acol + 2][arow] = av.z;
        As[acol + 3][arow] = av.w;
        float2 bv = *(const float2*)(g_wint + (k0 + brow) * N + col0 + bcol);
        Bs[brow][bcol]     = bv.x;
        Bs[brow][bcol + 1] = bv.y;
        __syncthreads();
        #pragma unroll
        for (int k = 0; k < BK; ++k) {
            float a[8], b[4];
            #pragma unroll
            for (int i = 0; i < 8; ++i) a[i] = As[k][ty * 8 + i];
            #pragma unroll
            for (int j = 0; j < 4; ++j) b[j] = Bs[k][tx * 4 + j];
            #pragma unroll
            for (int i = 0; i < 8; ++i)
                #pragma unroll
                for (int j = 0; j < 4; ++j)
                    acc[i][j] += a[i] * b[j];
        }
        __syncthreads();
    }
    const int nc = col0 + tx * 4;
    float4 bias = *(const float4*)(g_b1 + nc);
    #pragma unroll
    for (int i = 0; i < 8; ++i) {
        const int r = row0 + ty * 8 + i;
        float4 v;
        v.x = acc[i][0] + bias.x;
        v.y = acc[i][1] + bias.y;
        v.z = acc[i][2] + bias.z;
        v.w = acc[i][3] + bias.w;
        *(float4*)(g_hidden + r * HID_CH + nc) = v;
    }
}

// ---------------- 4: depthwise 3x3 + exact GELU ----------------
// grid (16,16, BATCH*6), block 256: c = tid&63 within 64-ch chunk, q = tid>>6
__global__ void __launch_bounds__(256)
dwconv_kernel(const float* __restrict__ w_dw) {
    __shared__ float sh[10][10][64];
    const int tid = threadIdx.x;
    const int c   = tid & 63;
    const int q   = tid >> 6;
    const int tx0 = blockIdx.x * 8;
    const int ty0 = blockIdx.y * 8;
    const int z   = blockIdx.z;
    const int b   = z / 6;
    const int cc  = z % 6;
    const int ch  = cc * 64;  // channel chunk base

    for (int i = tid; i < 10 * 10 * 64; i += 256) {
        const int cl = i & 63;
        const int s  = i >> 6;
        const int sx = s % 10;
        const int sy = s / 10;
        const int gy = ty0 + sy - 1;
        const int gx = tx0 + sx - 1;
        float v = 0.f;
        if ((unsigned)gy < 128u && (unsigned)gx < 128u)
            v = g_hidden[(((b * HP) + gy) * WP + gx) * HID_CH + ch + cl];
        sh[sy][sx][cl] = v;
    }
    __syncthreads();

    const int o = ch + c;
    float w[9];
    #pragma unroll
    for (int t = 0; t < 9; ++t) w[t] = w_dw[o * 9 + t];

    #pragma unroll
    for (int r = 0; r < 2; ++r) {
        const int oy = q * 2 + r;
        #pragma unroll
        for (int ox = 0; ox < 8; ++ox) {
            float s = 0.f;
            #pragma unroll
            for (int ky = 0; ky < 3; ++ky)
                #pragma unroll
                for (int kx = 0; kx < 3; ++kx)
                    s += w[ky * 3 + kx] * sh[oy + ky][ox + kx][c];
            // exact gelu: x * Phi(x)
            s = s * normcdff(s);
            g_hidden2[(((b * HP) + ty0 + oy) * WP + tx0 + ox) * HID_CH + o] = s;
        }
    }
}

// ---------------- 5: GEMM2 + residual + inverse pixel-shuffle write -------
// high channel m -> iwt input channel u' = 64+m -> k' = u'/64, j = u'%64,
// placed at phase (k'/2, k'%2), output channel j.
// blockIdx.y = m/64 = k'-1: 0 -> (0,1), 1 -> (1,0), 2 -> (1,1).
__global__ void __launch_bounds__(256)
gemm2_kernel(const float* __restrict__ res_scale, float* __restrict__ out) {
    __shared__ float As[BK][BM];
    __shared__ float Bs[BK][BN];
    const int K = HID_CH, N = IN_CH;
    const int tid  = threadIdx.x;
    const int row0 = blockIdx.x * BM;
    const int col0 = blockIdx.y * BN;
    const int tx = tid & 15, ty = tid >> 4;
    const int arow = tid >> 1, acol = (tid & 1) * 4;
    const int brow = tid >> 5, bcol = (tid & 31) * 2;
    float acc[8][4] = {};
    for (int k0 = 0; k0 < K; k0 += BK) {
        float4 av = *(const float4*)(g_hidden2 + (row0 + arow) * K + k0 + acol);
        As[acol + 0][arow] = av.x;
        As[acol + 1][arow] = av.y;
        As[acol + 2][arow] = av.z;
        As[acol + 3][arow] = av.w;
        float2 bv = *(const float2*)(g_woutt + (k0 + brow) * N + col0 + bcol);
        Bs[brow][bcol]     = bv.x;
        Bs[brow][bcol + 1] = bv.y;
        __syncthreads();
        #pragma unroll
        for (int k = 0; k < BK; ++k) {
            float a[8], b[4];
            #pragma unroll
            for (int i = 0; i < 8; ++i) a[i] = As[k][ty * 8 + i];
            #pragma unroll
            for (int j = 0; j < 4; ++j) b[j] = Bs[k][tx * 4 + j];
            #pragma unroll
            for (int i = 0; i < 8; ++i)
                #pragma unroll
                for (int j = 0; j < 4; ++j)
                    acc[i][j] += a[i] * b[j];
        }
        __syncthreads();
    }
    const float rs = res_scale[0];
    const int grp  = blockIdx.y;            // k'-1 : 0=LHo,1=HLo,2=HHo
    const int dy   = (grp != 0) ? 1 : 0;    // (0,1) (1,0) (1,1)
    const int dx   = (grp != 1) ? 1 : 0;
    const int nc   = col0 + tx * 4;         // high channel m
    const int c64  = tx * 4;                // output channel j = m % 64
    #pragma unroll
    for (int i = 0; i < 8; ++i) {
        const int r = row0 + ty * 8 + i;
        const int b  = r >> 14;
        const int y  = (r >> 7) & 127;
        const int xw = r & 127;
        const float4 hv = *(const float4*)(g_high + r * IN_CH + nc);
        float4 v;
        v.x = hv.x + rs * acc[i][0];
        v.y = hv.y + rs * acc[i][1];
        v.z = hv.z + rs * acc[i][2];
        v.w = hv.w + rs * acc[i][3];
        const int oy = 2 * y + dy;
        const int ox = 2 * xw + dx;
        *(float4*)(out + (((b * HIN) + oy) * WIN + ox) * DIM + c64) = v;
    }
}

// ---------------- launcher: bind inputs BY SIZE, positional fallback ------
extern "C" void kernel_launch(void* const* d_in, const int* in_sizes, int n_in,
                              void* d_out, int out_size) {
    const float* x     = nullptr;
    const float* w_dw  = nullptr;
    const float* rs    = nullptr;
    const float* p192[2]   = {nullptr, nullptr};
    const float* p73728[2] = {nullptr, nullptr};
    int n192 = 0, n73 = 0;
    for (int i = 0; i < n_in; ++i) {
        const float* p = (const float*)d_in[i];
        switch (in_sizes[i]) {
            case 33554432: x = p; break;
            case 3456:     w_dw = p; break;
            case 1:        rs = p; break;
            case 192:      if (n192 < 2) p192[n192++] = p; break;
            case 73728:    if (n73  < 2) p73728[n73++] = p; break;
            default: break;
        }
    }
    // Fallback: dict order (x, gamma, beta, w_in, w_dw, w_out, res_scale).
    if (!x || !w_dw || !rs || n192 < 2 || n73 < 2) {
        x         = (const float*)d_in[0];
        p192[0]   = (const float*)d_in[1];
        p192[1]   = (const float*)d_in[2];
        p73728[0] = (const float*)d_in[3];
        w_dw      = (const float*)d_in[4];
        p73728[1] = (const float*)d_in[5];
        rs        = (const float*)d_in[6];
    }
    const float* w_in  = p73728[0];
    const float* w_out = p73728[1];
    float* out = (float*)d_out;

    init_stats_kernel<<<1, 2 * IN_CH>>>();
    dwt_kernel<<<NPIX / 64, 64>>>(x, out);
    stats_fold_kernel<<<6, 64>>>(p192[0], p192[1], w_in, w_out);
    gemm1_kernel<<<dim3(NPIX / BM, HID_CH / BN), 256>>>();
    dwconv_kernel<<<dim3(16, 16, BATCH * 6), 256>>>(w_dw);
    gemm2_kernel<<<dim3(NPIX / BM, IN_CH / BN), 256>>>(rs, out);
}

// round 16
// speedup vs baseline: 1.4561x; 1.4561x over previous
#include <cuda_runtime.h>
#include <cuda_bf16.h>
#include <cstdint>

// Problem constants
#define BATCH   8
#define HIN     256
#define WIN     256
#define DIM     64
#define IN_CH   192      // 3*DIM
#define HID_CH  384      // 2*IN_CH
#define HP      128
#define WP      128
#define NPIX    (BATCH*HP*WP)   // 131072
#define BN_EPS  1e-5f

// ---------------- scratch ----------------
__device__ float g_high   [NPIX * IN_CH];    // fp32, residual + GEMM1 A source
__device__ float g_hidden [NPIX * HID_CH];   // fp32, GEMM1 out -> dwconv in
__device__ float g_hidden2[NPIX * HID_CH];   // fp32, dwconv out -> GEMM2 A source
__device__ float g_sum    [2 * IN_CH];
__device__ float g_b1     [HID_CH];
__device__ __nv_bfloat16 g_wb1_hi[HID_CH * IN_CH];  // folded w_in [o=384,c=192] (N-major)
__device__ __nv_bfloat16 g_wb1_lo[HID_CH * IN_CH];
__device__ __nv_bfloat16 g_wo_hi [IN_CH * HID_CH];  // w_out [192,384] (N-major)
__device__ __nv_bfloat16 g_wo_lo [IN_CH * HID_CH];

// ---------------- mma.sync helpers (baseline PTX, valid at compute_103) ---
__device__ __forceinline__ uint32_t smem_u32(const void* p) {
    uint32_t a;
    asm("{ .reg .u64 t; cvta.to.shared.u64 t, %1; cvt.u32.u64 %0, t; }"
        : "=r"(a) : "l"(p));
    return a;
}
__device__ __forceinline__ void ldsm4(uint32_t* r, uint32_t a) {
    asm volatile("ldmatrix.sync.aligned.m8n8.x4.shared.b16 {%0,%1,%2,%3}, [%4];"
        : "=r"(r[0]), "=r"(r[1]), "=r"(r[2]), "=r"(r[3]) : "r"(a));
}
__device__ __forceinline__ void mma16816(float* d, const uint32_t* a, const uint32_t* b) {
    asm volatile("mma.sync.aligned.m16n8k16.row.col.f32.bf16.bf16.f32 "
        "{%0,%1,%2,%3},{%4,%5,%6,%7},{%8,%9},{%0,%1,%2,%3};"
        : "+f"(d[0]), "+f"(d[1]), "+f"(d[2]), "+f"(d[3])
        : "r"(a[0]), "r"(a[1]), "r"(a[2]), "r"(a[3]), "r"(b[0]), "r"(b[1]));
}
__device__ __forceinline__ uint32_t pack_bf(float a, float b) {
    return (uint32_t)__bfloat16_as_ushort(__float2bfloat16_rn(a))
         | ((uint32_t)__bfloat16_as_ushort(__float2bfloat16_rn(b)) << 16);
}
// split 4 fp32 -> hi uint2 + lo uint2 (bf16 pairs, element order preserved)
__device__ __forceinline__ void split4(float4 f, uint2& h, uint2& l) {
    h.x = pack_bf(f.x, f.y);  h.y = pack_bf(f.z, f.w);
    float rx = f.x - __bfloat162float(__float2bfloat16_rn(f.x));
    float ry = f.y - __bfloat162float(__float2bfloat16_rn(f.y));
    float rz = f.z - __bfloat162float(__float2bfloat16_rn(f.z));
    float rw = f.w - __bfloat162float(__float2bfloat16_rn(f.w));
    l.x = pack_bf(rx, ry);    l.y = pack_bf(rz, rw);
}

#define S48 48   // smem row stride (bytes) for 16-bf16 rows: conflict-free ldmatrix

// ---------------- 0: zero stats ----------------
__global__ void init_stats_kernel() { g_sum[threadIdx.x] = 0.0f; }

// ---------------- 1: DWT (axis=2 semantics) + passthrough + stats ---------
__global__ void dwt_kernel(const float* __restrict__ x, float* __restrict__ out) {
    const int c  = threadIdx.x;
    const int p0 = blockIdx.x * 64;
    const bool hi = (c >= 16);
    float s0=0.f,s1=0.f,s2=0.f,s3=0.f, q0=0.f,q1=0.f,q2=0.f,q3=0.f;
    for (int pi = 0; pi < 64; ++pi) {
        const int p  = p0 + pi;
        const int b  = p >> 14;
        const int y  = (p >> 7) & 127;
        const int xw = p & 127;
        const int pixbase = (((b * HIN) + 2*y) * WIN + 2*xw) * DIM;
        const int ibase = pixbase + c;
        const float a  = x[ibase];
        const float bb = x[ibase + DIM];
        const float cc = x[ibase + WIN*DIM];
        const float dd = x[ibase + WIN*DIM + DIM];
        const float v0 = (a + bb + cc + dd) * 0.5f;
        const float v1 = (a - bb + cc - dd) * 0.5f;
        const float v2 = (a + bb - cc - dd) * 0.5f;
        const float v3 = (a - bb - cc + dd) * 0.5f;
        if (hi) {
            *(float4*)(g_high + (size_t)p * IN_CH + 4*(c - 16)) =
                make_float4(v0, v1, v2, v3);
            s0 += v0; q0 += v0*v0;  s1 += v1; q1 += v1*v1;
            s2 += v2; q2 += v2*v2;  s3 += v3; q3 += v3*v3;
        } else {
            *(float4*)(out + pixbase + 4*c) = make_float4(v0, v1, v2, v3);
        }
    }
    if (hi) {
        const int m0 = 4 * (c - 16);
        atomicAdd(&g_sum[m0 + 0], s0); atomicAdd(&g_sum[m0 + 1], s1);
        atomicAdd(&g_sum[m0 + 2], s2); atomicAdd(&g_sum[m0 + 3], s3);
        atomicAdd(&g_sum[IN_CH + m0 + 0], q0); atomicAdd(&g_sum[IN_CH + m0 + 1], q1);
        atomicAdd(&g_sum[IN_CH + m0 + 2], q2); atomicAdd(&g_sum[IN_CH + m0 + 3], q3);
    }
}

// ---------------- 2: BN fold -> split-bf16 weights ------------------------
__global__ void stats_fold_kernel(const float* __restrict__ cand0,
                                  const float* __restrict__ cand1,
                                  const float* __restrict__ w_in,
                                  const float* __restrict__ w_out) {
    __shared__ float s_scale[IN_CH];
    __shared__ float s_bias [IN_CH];
    const int tid = threadIdx.x;
    const float* gamma = (cand0[0] != 0.0f) ? cand0 : cand1;
    const float* beta  = (cand0[0] != 0.0f) ? cand1 : cand0;
    const float invN = 1.0f / (float)NPIX;
    for (int c = tid; c < IN_CH; c += 64) {
        float mean = g_sum[c] * invN;
        float var  = g_sum[IN_CH + c] * invN - mean * mean;
        float sc   = gamma[c] * rsqrtf(var + BN_EPS);
        s_scale[c] = sc;
        s_bias[c]  = beta[c] - mean * sc;
    }
    __syncthreads();
    const int o = blockIdx.x * 64 + tid;  // 0..383
    float bacc = 0.f;
    for (int c = 0; c < IN_CH; ++c) {
        float w0 = w_in[o * IN_CH + c];
        float w  = w0 * s_scale[c];
        bacc += w0 * s_bias[c];
        __nv_bfloat16 h = __float2bfloat16_rn(w);
        g_wb1_hi[o * IN_CH + c] = h;
        g_wb1_lo[o * IN_CH + c] = __float2bfloat16_rn(w - __bfloat162float(h));
    }
    g_b1[o] = bacc;
    if (o < IN_CH) {
        for (int k = 0; k < HID_CH; ++k) {
            float w = w_out[o * HID_CH + k];
            __nv_bfloat16 h = __float2bfloat16_rn(w);
            g_wo_hi[o * HID_CH + k] = h;
            g_wo_lo[o * HID_CH + k] = __float2bfloat16_rn(w - __bfloat162float(h));
        }
    }
}

// ---------------- 3: GEMM1 (mma.sync split-bf16) --------------------------
// C[NPIX,384] = high[NPIX,192] @ w_in'[384,192]^T + b1
// grid (1024, 3), block 256 (8 warps, 4x2). BM=128 BN=128 BK=16, 12 K-blocks.
__global__ void __launch_bounds__(256) gemm1_mma() {
    __shared__ __align__(16) uint8_t smem[4 * 128 * S48];  // Ah|Al|Bh|Bl (6KB each)
    const uint32_t sb  = smem_u32(smem);
    const uint32_t sAh = sb, sAl = sb + 6144, sBh = sb + 12288, sBl = sb + 18432;
    const int tid = threadIdx.x, wid = tid >> 5, lane = tid & 31;
    const int wm = wid >> 1, wn = wid & 1;
    const int row0 = blockIdx.x * 128, n0 = blockIdx.y * 128;
    const int lrow = tid >> 1, lhalf = tid & 1;

    // ldmatrix lane addressing (non-trans fragments for both A and B:
    // both are [row][k] layouts and mma needs k-consecutive pairs per reg)
    const uint32_t aOff = (uint32_t)((wm*32 + (lane&7) + ((lane>>3)&1)*8) * S48 + (lane>>4)*16);
    const uint32_t bOff = (uint32_t)((wn*64 + (lane&7) + ((lane>>4)&1)*8) * S48 + ((lane>>3)&1)*16);

    float acc[2][8][4] = {};

    // prefetch k-block 0
    const float* aP = g_high + (size_t)(row0 + lrow) * IN_CH + lhalf * 8;
    const __nv_bfloat16* bhP = g_wb1_hi + (size_t)(n0 + lrow) * IN_CH + lhalf * 8;
    const __nv_bfloat16* blP = g_wb1_lo + (size_t)(n0 + lrow) * IN_CH + lhalf * 8;
    float4 fa0 = *(const float4*)aP, fa1 = *(const float4*)(aP + 4);
    uint4 vbh = *(const uint4*)bhP, vbl = *(const uint4*)blP;

    for (int kb = 0; kb < 12; ++kb) {
        // stage current block to smem
        uint2 h0, l0, h1, l1;
        split4(fa0, h0, l0); split4(fa1, h1, l1);
        const uint32_t so = (uint32_t)(lrow * S48 + lhalf * 16);
        *(uint4*)(smem + (sAh - sb) + so) = make_uint4(h0.x, h0.y, h1.x, h1.y);
        *(uint4*)(smem + (sAl - sb) + so) = make_uint4(l0.x, l0.y, l1.x, l1.y);
        *(uint4*)(smem + (sBh - sb) + so) = vbh;
        *(uint4*)(smem + (sBl - sb) + so) = vbl;
        __syncthreads();

        // prefetch next block
        const int kn = (kb < 11) ? (kb + 1) * 16 : kb * 16;
        fa0 = *(const float4*)(aP + kn);
        fa1 = *(const float4*)(aP + kn + 4);
        vbh = *(const uint4*)(bhP + kn);
        vbl = *(const uint4*)(blP + kn);

        // 3 split passes: Ah*Bh, Ah*Bl, Al*Bh
#pragma unroll
        for (int p = 0; p < 3; ++p) {
            const uint32_t aB = (p == 2) ? sAl : sAh;
            const uint32_t bB = (p == 1) ? sBl : sBh;
            uint32_t af[2][4];
            ldsm4(af[0], aB + aOff);
            ldsm4(af[1], aB + aOff + 16 * S48);
#pragma unroll
            for (int nt4 = 0; nt4 < 4; ++nt4) {
                uint32_t bf4[4];
                ldsm4(bf4, bB + bOff + nt4 * 16 * S48);
                mma16816(acc[0][nt4*2],     af[0], bf4);
                mma16816(acc[0][nt4*2 + 1], af[0], bf4 + 2);
                mma16816(acc[1][nt4*2],     af[1], bf4);
                mma16816(acc[1][nt4*2 + 1], af[1], bf4 + 2);
            }
        }
        __syncthreads();
    }

    // epilogue: bias + store fp32
    const int lr = lane >> 2, lc = lane & 3;
#pragma unroll
    for (int mt = 0; mt < 2; ++mt) {
        const int r0 = row0 + wm*32 + mt*16 + lr;
#pragma unroll
        for (int nt = 0; nt < 8; ++nt) {
            const int col = n0 + wn*64 + nt*8 + lc*2;
            const float bx_ = g_b1[col], by_ = g_b1[col + 1];
            float* q0 = g_hidden + (size_t)r0 * HID_CH + col;
            *(float2*)q0 = make_float2(acc[mt][nt][0] + bx_, acc[mt][nt][1] + by_);
            *(float2*)(q0 + 8 * HID_CH) =
                make_float2(acc[mt][nt][2] + bx_, acc[mt][nt][3] + by_);
        }
    }
}

// ---------------- 4: depthwise 3x3 + exact GELU ---------------------------
__global__ void __launch_bounds__(256)
dwconv_kernel(const float* __restrict__ w_dw) {
    __shared__ float sh[10][10][64];
    const int tid = threadIdx.x;
    const int c   = tid & 63;
    const int q   = tid >> 6;
    const int tx0 = blockIdx.x * 8;
    const int ty0 = blockIdx.y * 8;
    const int z   = blockIdx.z;
    const int b   = z / 6;
    const int ch  = (z % 6) * 64;

    for (int i = tid; i < 10 * 10 * 64; i += 256) {
        const int cl = i & 63;
        const int s  = i >> 6;
        const int sx = s % 10;
        const int sy = s / 10;
        const int gy = ty0 + sy - 1;
        const int gx = tx0 + sx - 1;
        float v = 0.f;
        if ((unsigned)gy < 128u && (unsigned)gx < 128u)
            v = g_hidden[(((b * HP) + gy) * WP + gx) * HID_CH + ch + cl];
        sh[sy][sx][cl] = v;
    }
    __syncthreads();

    const int o = ch + c;
    float w[9];
#pragma unroll
    for (int t = 0; t < 9; ++t) w[t] = w_dw[o * 9 + t];

#pragma unroll
    for (int r = 0; r < 2; ++r) {
        const int oy = q * 2 + r;
#pragma unroll
        for (int ox = 0; ox < 8; ++ox) {
            float s = 0.f;
#pragma unroll
            for (int ky = 0; ky < 3; ++ky)
#pragma unroll
                for (int kx = 0; kx < 3; ++kx)
                    s += w[ky * 3 + kx] * sh[oy + ky][ox + kx][c];
            s = s * normcdff(s);
            g_hidden2[(((b * HP) + ty0 + oy) * WP + tx0 + ox) * HID_CH + o] = s;
        }
    }
}

// ---------------- 5: GEMM2 (mma.sync split-bf16) + residual + IWT ---------
// C[NPIX,192] = hidden2[NPIX,384] @ w_out[192,384]^T
// grid 1024, block 512 (16 warps, 4x4). BM=128 BN=192 BK=16, 24 K-blocks.
__global__ void __launch_bounds__(512) gemm2_mma(const float* __restrict__ res_scale,
                                                 float* __restrict__ out) {
    __shared__ __align__(16) uint8_t smem[2 * 128 * S48 + 2 * 192 * S48];  // 30.7KB
    const uint32_t sb  = smem_u32(smem);
    const uint32_t sAh = sb, sAl = sb + 6144, sBh = sb + 12288, sBl = sb + 12288 + 9216;
    const int tid = threadIdx.x, wid = tid >> 5, lane = tid & 31;
    const int wm = wid >> 2, wn = wid & 3;
    const int row0 = blockIdx.x * 128;

    const uint32_t aOff = (uint32_t)((wm*32 + (lane&7) + ((lane>>3)&1)*8) * S48 + (lane>>4)*16);
    const uint32_t bOff = (uint32_t)((wn*48 + (lane&7) + ((lane>>4)&1)*8) * S48 + ((lane>>3)&1)*16);

    float acc[2][6][4] = {};

    // A prefetch: thread -> (row = tid>>2, quarter = tid&3), 4 fp32
    const int arow = tid >> 2, aq = tid & 3;
    const float* aP = g_hidden2 + (size_t)(row0 + arow) * HID_CH + aq * 4;
    // B prefetch: threads < 384: (row = tid>>1, half), 8 bf16
    const int brow = tid >> 1, bhalf = tid & 1;
    const bool bAct = (tid < 384);
    const __nv_bfloat16* bhP = g_wo_hi + (size_t)brow * HID_CH + bhalf * 8;
    const __nv_bfloat16* blP = g_wo_lo + (size_t)brow * HID_CH + bhalf * 8;

    float4 fa = *(const float4*)aP;
    uint4 vbh = bAct ? *(const uint4*)bhP : make_uint4(0,0,0,0);
    uint4 vbl = bAct ? *(const uint4*)blP : make_uint4(0,0,0,0);

    for (int kb = 0; kb < 24; ++kb) {
        uint2 h, l;
        split4(fa, h, l);
        *(uint2*)(smem + (sAh - sb) + arow * S48 + aq * 8) = h;
        *(uint2*)(smem + (sAl - sb) + arow * S48 + aq * 8) = l;
        if (bAct) {
            *(uint4*)(smem + (sBh - sb) + brow * S48 + bhalf * 16) = vbh;
            *(uint4*)(smem + (sBl - sb) + brow * S48 + bhalf * 16) = vbl;
        }
        __syncthreads();

        const int kn = (kb < 23) ? (kb + 1) * 16 : kb * 16;
        fa = *(const float4*)(aP + kn);
        if (bAct) {
            vbh = *(const uint4*)(bhP + kn);
            vbl = *(const uint4*)(blP + kn);
        }

#pragma unroll
        for (int p = 0; p < 3; ++p) {
            const uint32_t aB = (p == 2) ? sAl : sAh;
            const uint32_t bB = (p == 1) ? sBl : sBh;
            uint32_t af[2][4];
            ldsm4(af[0], aB + aOff);
            ldsm4(af[1], aB + aOff + 16 * S48);
#pragma unroll
            for (int nt4 = 0; nt4 < 3; ++nt4) {
                uint32_t bf4[4];
                ldsm4(bf4, bB + bOff + nt4 * 16 * S48);
                mma16816(acc[0][nt4*2],     af[0], bf4);
                mma16816(acc[0][nt4*2 + 1], af[0], bf4 + 2);
                mma16816(acc[1][nt4*2],     af[1], bf4);
                mma16816(acc[1][nt4*2 + 1], af[1], bf4 + 2);
            }
        }
        __syncthreads();
    }

    // epilogue: residual + inverse pixel-shuffle
    const float rs = res_scale[0];
    const int lr = lane >> 2, lc = lane & 3;
#pragma unroll
    for (int mt = 0; mt < 2; ++mt) {
#pragma unroll
        for (int nt = 0; nt < 6; ++nt) {
            const int c   = wn*48 + nt*8 + lc*2;     // high channel m (even)
            const int grp = c >> 6;                  // 0->(0,1) 1->(1,0) 2->(1,1)
            const int dy  = (grp != 0) ? 1 : 0;
            const int dx  = (grp != 1) ? 1 : 0;
            const int c64 = c & 63;
#pragma unroll
            for (int half = 0; half < 2; ++half) {
                const int p  = row0 + wm*32 + mt*16 + lr + half*8;
                const int b  = p >> 14;
                const int y  = (p >> 7) & 127;
                const int xw = p & 127;
                const float2 hv = *(const float2*)(g_high + (size_t)p * IN_CH + c);
                float2 v;
                v.x = hv.x + rs * acc[mt][nt][half*2 + 0];
                v.y = hv.y + rs * acc[mt][nt][half*2 + 1];
                *(float2*)(out + (((b * HIN) + 2*y + dy) * WIN + 2*xw + dx) * DIM + c64) = v;
            }
        }
    }
}

// ---------------- launcher ----------------
extern "C" void kernel_launch(void* const* d_in, const int* in_sizes, int n_in,
                              void* d_out, int out_size) {
    const float* x     = nullptr;
    const float* w_dw  = nullptr;
    const float* rs    = nullptr;
    const float* p192[2]   = {nullptr, nullptr};
    const float* p73728[2] = {nullptr, nullptr};
    int n192 = 0, n73 = 0;
    for (int i = 0; i < n_in; ++i) {
        const float* p = (const float*)d_in[i];
        switch (in_sizes[i]) {
            case 33554432: x = p; break;
            case 3456:     w_dw = p; break;
            case 1:        rs = p; break;
            case 192:      if (n192 < 2) p192[n192++] = p; break;
            case 73728:    if (n73  < 2) p73728[n73++] = p; break;
            default: break;
        }
    }
    if (!x || !w_dw || !rs || n192 < 2 || n73 < 2) {
        x         = (const float*)d_in[0];
        p192[0]   = (const float*)d_in[1];
        p192[1]   = (const float*)d_in[2];
        p73728[0] = (const float*)d_in[3];
        w_dw      = (const float*)d_in[4];
        p73728[1] = (const float*)d_in[5];
        rs        = (const float*)d_in[6];
    }
    const float* w_in  = p73728[0];
    const float* w_out = p73728[1];
    float* out = (float*)d_out;

    init_stats_kernel<<<1, 2 * IN_CH>>>();
    dwt_kernel<<<NPIX / 64, 64>>>(x, out);
    stats_fold_kernel<<<6, 64>>>(p192[0], p192[1], w_in, w_out);
    gemm1_mma<<<dim3(NPIX / 128, 3), 256>>>();
    dwconv_kernel<<<dim3(16, 16, BATCH * 6), 256>>>(w_dw);
    gemm2_mma<<<NPIX / 128, 512>>>(rs, out);
}